// round 3
// baseline (speedup 1.0000x reference)
#include <cuda_runtime.h>
#include <cuda_bf16.h>
#include <cstdint>

#define NW 10
#define DIM 1024
#define HID 64

// W stored directly in mma.m16n8k16 B-fragment layout (hi/lo bf16 split).
// u32 fragment index = ((tile*4 + chunk)*32 + lane)*2 + s ; bf16 half h in [0,1].
// tile = n>>3 (n = 2*i + re/im, 2048 columns), chunk = c>>4 (c = feature 0..63),
// lane = (n&7)*4 + ((c&7)>>1), s = (c&15)>>3, h = c&1.
__device__ __align__(16) unsigned short WBH[131072];
__device__ __align__(16) unsigned short WBL[131072];

// ---------------------------------------------------------------------------
// Circuit kernel: block c simulates U|e_c>, scatters column c into fragments.
// ---------------------------------------------------------------------------
__device__ __forceinline__ void gate1q(float2* psi, int tid, int bit,
    float g00x, float g00y, float g01x, float g01y,
    float g10x, float g10y, float g11x, float g11y)
{
    const int lowmask = bit - 1;
    const int i0 = ((tid & ~lowmask) << 1) | (tid & lowmask);
    const int i1 = i0 | bit;
    const float2 a = psi[i0], b = psi[i1];
    float2 n0, n1;
    n0.x = g00x*a.x - g00y*a.y + g01x*b.x - g01y*b.y;
    n0.y = g00x*a.y + g00y*a.x + g01x*b.y + g01y*b.x;
    n1.x = g10x*a.x - g10y*a.y + g11x*b.x - g11y*b.y;
    n1.y = g10x*a.y + g10y*a.x + g11x*b.y + g11y*b.x;
    psi[i0] = n0; psi[i1] = n1;
}

__device__ __forceinline__ void split_bf(float v, __nv_bfloat16& h, __nv_bfloat16& l) {
    h = __float2bfloat16(v);
    l = __float2bfloat16(v - __bfloat162float(h));
}

__global__ void qsa_circuit(const float* __restrict__ rx0,
                            const float* __restrict__ ry0,
                            const float* __restrict__ ry1)
{
    __shared__ float2 psi[DIM];
    const int tid = threadIdx.x;   // 512
    const int c = blockIdx.x;      // 0..63 (feature / unitary column)

    psi[tid]       = make_float2(0.f, 0.f);
    psi[tid + 512] = make_float2(0.f, 0.f);
    __syncthreads();
    if (tid == 0) psi[c] = make_float2(1.f, 0.f);
    __syncthreads();

    for (int j = 0; j < NW; j++) {
        const int bit = 1 << (NW - 1 - j);
        float s, cc;
        sincosf(0.5f * rx0[j], &s, &cc);
        gate1q(psi, tid, bit, cc, 0.f, 0.f, -s, 0.f, -s, cc, 0.f);
        __syncthreads();
        sincosf(0.5f * ry0[j], &s, &cc);
        gate1q(psi, tid, bit, cc, 0.f, -s, 0.f, s, 0.f, cc, 0.f);
        __syncthreads();
    }
    for (int j = 0; j < NW; j++) {
        const int cbit = 1 << (NW - 1 - j);
        const int tbit = 1 << (NW - 1 - ((j + 1) % NW));
        #pragma unroll
        for (int rep = 0; rep < 2; rep++) {
            const int i = tid + rep * 512;
            if ((i & cbit) && !(i & tbit)) {
                const float2 t = psi[i];
                psi[i] = psi[i | tbit];
                psi[i | tbit] = t;
            }
        }
        __syncthreads();
    }
    for (int j = 0; j < NW; j++) {
        const int bit = 1 << (NW - 1 - j);
        float s, cc;
        sincosf(0.5f * ry1[j], &s, &cc);
        gate1q(psi, tid, bit, cc, 0.f, -s, 0.f, s, 0.f, cc, 0.f);
        __syncthreads();
    }

    // scatter column c into B-fragment layout
    const int chunk = c >> 4;
    const int kk = c & 15;
    const int s  = kk >> 3;
    const int lq = (kk & 7) >> 1;
    const int hh = kk & 1;
    #pragma unroll
    for (int rep = 0; rep < 2; rep++) {
        const int i = tid + rep * 512;
        const float2 v = psi[i];
        #pragma unroll
        for (int p = 0; p < 2; p++) {
            const float val = p ? v.y : v.x;
            __nv_bfloat16 h, l;
            split_bf(val, h, l);
            const int n = 2 * i + p;
            const int tile = n >> 3;
            const int lane = (n & 7) * 4 + lq;
            const int idx = (((tile * 4 + chunk) * 32 + lane) * 2 + s) * 2 + hh;
            WBH[idx] = __bfloat16_as_ushort(h);
            WBL[idx] = __bfloat16_as_ushort(l);
        }
    }
}

// ---------------------------------------------------------------------------
// HMMA helper
// ---------------------------------------------------------------------------
__device__ __forceinline__ void mma16816(float& c0, float& c1, float& c2, float& c3,
    uint32_t a0, uint32_t a1, uint32_t a2, uint32_t a3, uint32_t b0, uint32_t b1)
{
    asm volatile(
        "mma.sync.aligned.m16n8k16.row.col.f32.bf16.bf16.f32 "
        "{%0,%1,%2,%3}, {%4,%5,%6,%7}, {%8,%9}, {%0,%1,%2,%3};"
        : "+f"(c0), "+f"(c1), "+f"(c2), "+f"(c3)
        : "r"(a0), "r"(a1), "r"(a2), "r"(a3), "r"(b0), "r"(b1));
}

__device__ __forceinline__ uint32_t pack_hi(float y0, float y1) {
    return ((uint32_t)__bfloat16_as_ushort(__float2bfloat16(y1)) << 16)
         |  __bfloat16_as_ushort(__float2bfloat16(y0));
}
__device__ __forceinline__ uint32_t pack_lo(float y0, float y1) {
    __nv_bfloat16 h0 = __float2bfloat16(y0);
    __nv_bfloat16 h1 = __float2bfloat16(y1);
    __nv_bfloat16 l0 = __float2bfloat16(y0 - __bfloat162float(h0));
    __nv_bfloat16 l1 = __float2bfloat16(y1 - __bfloat162float(h1));
    return ((uint32_t)__bfloat16_as_ushort(l1) << 16) | __bfloat16_as_ushort(l0);
}

// ---------------------------------------------------------------------------
// Main kernel: 128 tokens/CTA, 8 warps, each warp owns 16 tokens.
// ---------------------------------------------------------------------------
__global__ void __launch_bounds__(256) qsa_main(const float* __restrict__ x,
                                                float* __restrict__ out)
{
    __shared__ float Y[128][65];
    const int tid  = threadIdx.x;
    const int w    = tid >> 5;
    const int lane = tid & 31;
    const int m0   = blockIdx.x * 128;

    // --- load + L2-normalize 128 tokens into smem ---
    {
        const int tk = tid >> 1;       // token 0..127
        const int half = tid & 1;      // 32 floats each
        const float4* xr = reinterpret_cast<const float4*>(
            x + (size_t)(m0 + tk) * HID + half * 32);
        float4 f[8];
        float ssq = 0.f;
        #pragma unroll
        for (int i = 0; i < 8; i++) {
            f[i] = xr[i];
            ssq += f[i].x*f[i].x + f[i].y*f[i].y + f[i].z*f[i].z + f[i].w*f[i].w;
        }
        ssq += __shfl_xor_sync(0xffffffffu, ssq, 1);
        const float rn = rsqrtf(ssq);
        #pragma unroll
        for (int i = 0; i < 8; i++) {
            Y[tk][half*32 + 4*i + 0] = f[i].x * rn;
            Y[tk][half*32 + 4*i + 1] = f[i].y * rn;
            Y[tk][half*32 + 4*i + 2] = f[i].z * rn;
            Y[tk][half*32 + 4*i + 3] = f[i].w * rn;
        }
    }
    __syncthreads();

    // --- build A fragments (16 tokens x 64 k, hi/lo) : 4 chunks x 4 regs ---
    uint32_t Ah[4][4], Al[4][4];
    {
        const int r0 = w * 16 + (lane >> 2);
        const int q2 = (lane & 3) * 2;
        #pragma unroll
        for (int ch = 0; ch < 4; ch++)
            #pragma unroll
            for (int rg = 0; rg < 4; rg++) {
                const int row = r0 + 8 * (rg & 1);
                const int k = ch * 16 + q2 + 8 * (rg >> 1);
                const float y0 = Y[row][k], y1 = Y[row][k+1];
                Ah[ch][rg] = pack_hi(y0, y1);
                Al[ch][rg] = pack_lo(y0, y1);
            }
    }

    // --- main loop: 256 N-tiles (8 cols = 4 amplitudes each) ---
    float q[2][32];
    #pragma unroll
    for (int r = 0; r < 2; r++)
        #pragma unroll
        for (int i = 0; i < 32; i++) q[r][i] = 0.f;

    const uint2* WH2 = reinterpret_cast<const uint2*>(WBH);
    const uint2* WL2 = reinterpret_cast<const uint2*>(WBL);

    for (int t0 = 0; t0 < 256; t0 += 32) {
        #pragma unroll
        for (int u = 0; u < 32; u++) {
            const int tile = t0 + u;
            const uint2* pH = WH2 + tile * 128 + lane;
            const uint2* pL = WL2 + tile * 128 + lane;
            float c0 = 0.f, c1 = 0.f, c2 = 0.f, c3 = 0.f;
            #pragma unroll
            for (int ch = 0; ch < 4; ch++) {
                const uint2 bh = pH[ch * 32];
                const uint2 bl = pL[ch * 32];
                mma16816(c0,c1,c2,c3, Ah[ch][0],Ah[ch][1],Ah[ch][2],Ah[ch][3], bh.x, bh.y);
                mma16816(c0,c1,c2,c3, Al[ch][0],Al[ch][1],Al[ch][2],Al[ch][3], bh.x, bh.y);
                mma16816(c0,c1,c2,c3, Ah[ch][0],Ah[ch][1],Ah[ch][2],Ah[ch][3], bl.x, bl.y);
            }
            // lane holds (re,im) of amplitude i = 4*tile + (lane&3), rows r0 and r0+8
            q[0][u] = fmaf(c0, c0, fmaf(c1, c1, q[0][u]));
            q[1][u] = fmaf(c2, c2, fmaf(c3, c3, q[1][u]));
        }
    }

    // --- fast Walsh-Hadamard over j (7 bits): j = 4*t32 + (lane&3) ---
    // local stages: j bits 2..6 (t32 bits 0..4)
    #pragma unroll
    for (int r = 0; r < 2; r++)
        #pragma unroll
        for (int e = 0; e < 5; e++) {
            const int str = 1 << e;
            #pragma unroll
            for (int i = 0; i < 32; i++)
                if ((i & str) == 0) {
                    const float a = q[r][i], b = q[r][i + str];
                    q[r][i] = a + b;
                    q[r][i + str] = a - b;
                }
        }
    // lane stages: j bits 0,1
    #pragma unroll
    for (int r = 0; r < 2; r++)
        #pragma unroll
        for (int i = 0; i < 32; i++) {
            float v = q[r][i];
            float p = __shfl_xor_sync(0xffffffffu, v, 1);
            v = (lane & 1) ? (p - v) : (v + p);
            p = __shfl_xor_sync(0xffffffffu, v, 2);
            v = (lane & 2) ? (p - v) : (v + p);
            q[r][i] = v;
        }

    // --- store: out[token][k] = F[k+1], k = 4*t32 + (lane&3) - 1 ---
    #pragma unroll
    for (int r = 0; r < 2; r++) {
        const int token = m0 + w * 16 + (lane >> 2) + 8 * r;
        float* orow = out + (size_t)token * HID;
        #pragma unroll
        for (int t32 = 0; t32 <= 16; t32++) {
            const int m = 4 * t32 + (lane & 3);
            if (m >= 1 && m <= 64)
                orow[m - 1] = q[r][t32];
        }
    }
}

extern "C" void kernel_launch(void* const* d_in, const int* in_sizes, int n_in,
                              void* d_out, int out_size)
{
    const float* x   = (const float*)d_in[0];
    const float* rx0 = (const float*)d_in[1];
    const float* ry0 = (const float*)d_in[2];
    const float* ry1 = (const float*)d_in[3];
    float* out = (float*)d_out;

    const int M = in_sizes[0] / HID;   // 16384 tokens

    qsa_circuit<<<HID, 512>>>(rx0, ry0, ry1);     // W -> HMMA B-fragment layout
    qsa_main<<<M / 128, 256>>>(x, out);           // HMMA GEMM + fold + WHT epilogue
}

// round 4
// speedup vs baseline: 3.5195x; 3.5195x over previous
#include <cuda_runtime.h>
#include <cuda_bf16.h>
#include <cstdint>

#define NW 10
#define DIM 1024
#define HID 64

// W packed for the main loop: uint4 index = tile*64 + (chunk>>1)*32 + lane.
// Within a uint4 (4 u32): [(chunk&1)*2 + s], each u32 = two bf16 (h=0 low, h=1 high).
// B-frag mapping (validated in R3): lane = (n&7)*4 + ((c&7)>>1), s = (c>>3)&1, h = c&1,
// tile = n>>3, chunk = c>>4, n = 2*i + (0:Re,1:Im), c = feature.
__device__ __align__(16) unsigned short WPH[131072];
__device__ __align__(16) unsigned short WPL[131072];

// ---------------------------------------------------------------------------
// Circuit kernel: block c simulates U|e_c>, scatters column c into fragments.
// ---------------------------------------------------------------------------
__device__ __forceinline__ void gate1q(float2* psi, int tid, int bit,
    float g00x, float g00y, float g01x, float g01y,
    float g10x, float g10y, float g11x, float g11y)
{
    const int lowmask = bit - 1;
    const int i0 = ((tid & ~lowmask) << 1) | (tid & lowmask);
    const int i1 = i0 | bit;
    const float2 a = psi[i0], b = psi[i1];
    float2 n0, n1;
    n0.x = g00x*a.x - g00y*a.y + g01x*b.x - g01y*b.y;
    n0.y = g00x*a.y + g00y*a.x + g01x*b.y + g01y*b.x;
    n1.x = g10x*a.x - g10y*a.y + g11x*b.x - g11y*b.y;
    n1.y = g10x*a.y + g10y*a.x + g11x*b.y + g11y*b.x;
    psi[i0] = n0; psi[i1] = n1;
}

__global__ void qsa_circuit(const float* __restrict__ rx0,
                            const float* __restrict__ ry0,
                            const float* __restrict__ ry1)
{
    __shared__ float2 psi[DIM];
    const int tid = threadIdx.x;   // 512
    const int c = blockIdx.x;      // 0..63 (feature / unitary column)

    psi[tid]       = make_float2(0.f, 0.f);
    psi[tid + 512] = make_float2(0.f, 0.f);
    __syncthreads();
    if (tid == 0) psi[c] = make_float2(1.f, 0.f);
    __syncthreads();

    for (int j = 0; j < NW; j++) {
        const int bit = 1 << (NW - 1 - j);
        float s, cc;
        sincosf(0.5f * rx0[j], &s, &cc);
        gate1q(psi, tid, bit, cc, 0.f, 0.f, -s, 0.f, -s, cc, 0.f);
        __syncthreads();
        sincosf(0.5f * ry0[j], &s, &cc);
        gate1q(psi, tid, bit, cc, 0.f, -s, 0.f, s, 0.f, cc, 0.f);
        __syncthreads();
    }
    for (int j = 0; j < NW; j++) {
        const int cbit = 1 << (NW - 1 - j);
        const int tbit = 1 << (NW - 1 - ((j + 1) % NW));
        #pragma unroll
        for (int rep = 0; rep < 2; rep++) {
            const int i = tid + rep * 512;
            if ((i & cbit) && !(i & tbit)) {
                const float2 t = psi[i];
                psi[i] = psi[i | tbit];
                psi[i | tbit] = t;
            }
        }
        __syncthreads();
    }
    for (int j = 0; j < NW; j++) {
        const int bit = 1 << (NW - 1 - j);
        float s, cc;
        sincosf(0.5f * ry1[j], &s, &cc);
        gate1q(psi, tid, bit, cc, 0.f, -s, 0.f, s, 0.f, cc, 0.f);
        __syncthreads();
    }

    // scatter column c into packed B-fragment layout
    const int chunk = c >> 4;
    const int s  = (c >> 3) & 1;
    const int lq = (c & 7) >> 1;
    const int h  = c & 1;
    #pragma unroll
    for (int rep = 0; rep < 2; rep++) {
        const int i = tid + rep * 512;
        const float2 v = psi[i];
        #pragma unroll
        for (int p = 0; p < 2; p++) {
            const float val = p ? v.y : v.x;
            __nv_bfloat16 hi = __float2bfloat16(val);
            __nv_bfloat16 lo = __float2bfloat16(val - __bfloat162float(hi));
            const int n = 2 * i + p;
            const int tile = n >> 3;
            const int lane = (n & 7) * 4 + lq;
            const int idx = ((tile * 64 + (chunk >> 1) * 32 + lane) * 4
                             + (chunk & 1) * 2 + s) * 2 + h;
            WPH[idx] = __bfloat16_as_ushort(hi);
            WPL[idx] = __bfloat16_as_ushort(lo);
        }
    }
}

// ---------------------------------------------------------------------------
// HMMA helper
// ---------------------------------------------------------------------------
__device__ __forceinline__ void mma16816(float* c,
    uint32_t a0, uint32_t a1, uint32_t a2, uint32_t a3, uint32_t b0, uint32_t b1)
{
    asm volatile(
        "mma.sync.aligned.m16n8k16.row.col.f32.bf16.bf16.f32 "
        "{%0,%1,%2,%3}, {%4,%5,%6,%7}, {%8,%9}, {%0,%1,%2,%3};"
        : "+f"(c[0]), "+f"(c[1]), "+f"(c[2]), "+f"(c[3])
        : "r"(a0), "r"(a1), "r"(a2), "r"(a3), "r"(b0), "r"(b1));
}

// ---------------------------------------------------------------------------
// Main kernel: 32 tokens/CTA, 8 warps; warp w handles tiles w + 8t (t=0..31)
// for all 32 tokens. grid = 512.
// ---------------------------------------------------------------------------
__global__ void __launch_bounds__(256, 1) qsa_main(const float* __restrict__ x,
                                                   float* __restrict__ out)
{
    __shared__ float Y[32][64];
    __shared__ float Q[32][132];
    const int tid  = threadIdx.x;
    const int w    = tid >> 5;
    const int lane = tid & 31;
    const int m0   = blockIdx.x * 32;

    // --- load + L2-normalize 32 tokens ---
    {
        const int tk = tid >> 3;          // token 0..31
        const int pp = tid & 7;           // 8 floats each
        const float2* xr = reinterpret_cast<const float2*>(
            x + (size_t)(m0 + tk) * HID + pp * 8);
        float2 f[4];
        float ssq = 0.f;
        #pragma unroll
        for (int i = 0; i < 4; i++) {
            f[i] = xr[i];
            ssq += f[i].x*f[i].x + f[i].y*f[i].y;
        }
        ssq += __shfl_xor_sync(0xffffffffu, ssq, 1);
        ssq += __shfl_xor_sync(0xffffffffu, ssq, 2);
        ssq += __shfl_xor_sync(0xffffffffu, ssq, 4);
        const float rn = rsqrtf(ssq);
        #pragma unroll
        for (int i = 0; i < 4; i++) {
            Y[tk][pp*8 + 2*i + 0] = f[i].x * rn;
            Y[tk][pp*8 + 2*i + 1] = f[i].y * rn;
        }
    }
    __syncthreads();

    // --- A fragments: 2 token-groups x 4 k-chunks x 4 regs, hi/lo ---
    uint32_t Ah[2][4][4], Al[2][4][4];
    {
        const int r0 = lane >> 2;
        const int q2 = (lane & 3) * 2;
        #pragma unroll
        for (int g = 0; g < 2; g++)
            #pragma unroll
            for (int ch = 0; ch < 4; ch++)
                #pragma unroll
                for (int rg = 0; rg < 4; rg++) {
                    const int row = g*16 + r0 + 8*(rg & 1);
                    const int k = ch*16 + q2 + 8*(rg >> 1);
                    const float y0 = Y[row][k], y1 = Y[row][k+1];
                    __nv_bfloat16 h0 = __float2bfloat16(y0);
                    __nv_bfloat16 h1 = __float2bfloat16(y1);
                    __nv_bfloat16 l0 = __float2bfloat16(y0 - __bfloat162float(h0));
                    __nv_bfloat16 l1 = __float2bfloat16(y1 - __bfloat162float(h1));
                    Ah[g][ch][rg] = ((uint32_t)__bfloat16_as_ushort(h1) << 16)
                                  |  __bfloat16_as_ushort(h0);
                    Al[g][ch][rg] = ((uint32_t)__bfloat16_as_ushort(l1) << 16)
                                  |  __bfloat16_as_ushort(l0);
                }
    }

    // --- main loop: 32 tiles, fold into q[g][row][s], s = t&3 ---
    float q[2][2][4];
    #pragma unroll
    for (int g = 0; g < 2; g++)
        #pragma unroll
        for (int r = 0; r < 2; r++)
            #pragma unroll
            for (int s = 0; s < 4; s++) q[g][r][s] = 0.f;

    const uint4* PH = reinterpret_cast<const uint4*>(WPH);
    const uint4* PL = reinterpret_cast<const uint4*>(WPL);

    #pragma unroll 2
    for (int t = 0; t < 32; t++) {
        const int tile = w + 8*t;
        const uint4 bh0 = PH[tile*64 + lane];        // chunks 0,1
        const uint4 bh1 = PH[tile*64 + 32 + lane];   // chunks 2,3
        const uint4 bl0 = PL[tile*64 + lane];
        const uint4 bl1 = PL[tile*64 + 32 + lane];
        const int s = t & 3;

        #pragma unroll
        for (int g = 0; g < 2; g++) {
            float hh[4] = {0.f,0.f,0.f,0.f};
            float lh[4] = {0.f,0.f,0.f,0.f};
            float hl[4] = {0.f,0.f,0.f,0.f};
            // 3 independent chains of 4 MMAs
            mma16816(hh, Ah[g][0][0],Ah[g][0][1],Ah[g][0][2],Ah[g][0][3], bh0.x, bh0.y);
            mma16816(lh, Al[g][0][0],Al[g][0][1],Al[g][0][2],Al[g][0][3], bh0.x, bh0.y);
            mma16816(hl, Ah[g][0][0],Ah[g][0][1],Ah[g][0][2],Ah[g][0][3], bl0.x, bl0.y);
            mma16816(hh, Ah[g][1][0],Ah[g][1][1],Ah[g][1][2],Ah[g][1][3], bh0.z, bh0.w);
            mma16816(lh, Al[g][1][0],Al[g][1][1],Al[g][1][2],Al[g][1][3], bh0.z, bh0.w);
            mma16816(hl, Ah[g][1][0],Ah[g][1][1],Ah[g][1][2],Ah[g][1][3], bl0.z, bl0.w);
            mma16816(hh, Ah[g][2][0],Ah[g][2][1],Ah[g][2][2],Ah[g][2][3], bh1.x, bh1.y);
            mma16816(lh, Al[g][2][0],Al[g][2][1],Al[g][2][2],Al[g][2][3], bh1.x, bh1.y);
            mma16816(hl, Ah[g][2][0],Ah[g][2][1],Ah[g][2][2],Ah[g][2][3], bl1.x, bl1.y);
            mma16816(hh, Ah[g][3][0],Ah[g][3][1],Ah[g][3][2],Ah[g][3][3], bh1.z, bh1.w);
            mma16816(lh, Al[g][3][0],Al[g][3][1],Al[g][3][2],Al[g][3][3], bh1.z, bh1.w);
            mma16816(hl, Ah[g][3][0],Ah[g][3][1],Ah[g][3][2],Ah[g][3][3], bl1.z, bl1.w);

            const float c0 = hh[0] + lh[0] + hl[0];
            const float c1 = hh[1] + lh[1] + hl[1];
            const float c2 = hh[2] + lh[2] + hl[2];
            const float c3 = hh[3] + lh[3] + hl[3];
            q[g][0][s] = fmaf(c0, c0, fmaf(c1, c1, q[g][0][s]));
            q[g][1][s] = fmaf(c2, c2, fmaf(c3, c3, q[g][1][s]));
        }
    }

    // --- scatter q into Q[token][j], j = 4w + 32s + (lane&3); disjoint per warp ---
    #pragma unroll
    for (int g = 0; g < 2; g++)
        #pragma unroll
        for (int r = 0; r < 2; r++)
            #pragma unroll
            for (int s = 0; s < 4; s++) {
                const int tok = g*16 + r*8 + (lane >> 2);
                const int j = 4*w + 32*s + (lane & 3);
                Q[tok][j] = q[g][r][s];
            }
    __syncthreads();

    // --- 128-pt WHT per token (warp w: tokens 4w..4w+3), store out[k] = F[k+1] ---
    #pragma unroll
    for (int tt = 0; tt < 4; tt++) {
        const int tok = w*4 + tt;
        float f0 = Q[tok][lane];
        float f1 = Q[tok][lane + 32];
        float f2 = Q[tok][lane + 64];
        float f3 = Q[tok][lane + 96];
        // bit5 (32): (f0,f1), (f2,f3)
        float a0 = f0 + f1, a1 = f0 - f1, a2 = f2 + f3, a3 = f2 - f3;
        // bit6 (64): (a0,a2), (a1,a3)
        f0 = a0 + a2; f2 = a0 - a2; f1 = a1 + a3; f3 = a1 - a3;
        // bits 0..4 via shfl butterflies
        #pragma unroll
        for (int e = 1; e <= 16; e <<= 1) {
            float p;
            p = __shfl_xor_sync(0xffffffffu, f0, e); f0 = (lane & e) ? (p - f0) : (f0 + p);
            p = __shfl_xor_sync(0xffffffffu, f1, e); f1 = (lane & e) ? (p - f1) : (f1 + p);
            p = __shfl_xor_sync(0xffffffffu, f2, e); f2 = (lane & e) ? (p - f2) : (f2 + p);
            p = __shfl_xor_sync(0xffffffffu, f3, e); f3 = (lane & e) ? (p - f3) : (f3 + p);
        }
        float* orow = out + (size_t)(m0 + tok) * HID;
        if (lane >= 1) orow[lane - 1] = f0;     // F[1..31]  -> k 0..30
        orow[lane + 31] = f1;                   // F[32..63] -> k 31..62
        if (lane == 0) orow[63] = f2;           // F[64]     -> k 63
    }
}

extern "C" void kernel_launch(void* const* d_in, const int* in_sizes, int n_in,
                              void* d_out, int out_size)
{
    const float* x   = (const float*)d_in[0];
    const float* rx0 = (const float*)d_in[1];
    const float* ry0 = (const float*)d_in[2];
    const float* ry1 = (const float*)d_in[3];
    float* out = (float*)d_out;

    const int M = in_sizes[0] / HID;   // 16384 tokens

    qsa_circuit<<<HID, 512>>>(rx0, ry0, ry1);   // W -> packed HMMA B fragments
    qsa_main<<<M / 32, 256>>>(x, out);          // HMMA GEMM + fold + WHT epilogue
}

// round 5
// speedup vs baseline: 6.5860x; 1.8713x over previous
#include <cuda_runtime.h>
#include <cuda_bf16.h>
#include <cstdint>

#define NW 10
#define DIM 1024
#define HID 64

// W packed in HMMA B-fragment layout (validated R3/R4), + 4096 shorts padding so
// the main loop's last prefetch can read one tile beyond without bounds checks.
// uint4 index = tile*64 + (chunk>>1)*32 + lane ; u32 slot = (chunk&1)*2 + s ;
// lane = (n&7)*4 + ((c&7)>>1), s = (c>>3)&1, h = c&1, tile = n>>3, chunk = c>>4,
// n = 2*i + (0:Re,1:Im), c = feature.
__device__ __align__(16) unsigned short WPH[131072 + 4096];
__device__ __align__(16) unsigned short WPL[131072 + 4096];

// ---------------------------------------------------------------------------
// Circuit kernel: block c simulates U|e_c>, scatters column c into fragments.
// ---------------------------------------------------------------------------
__device__ __forceinline__ void gate1q(float2* psi, int tid, int bit,
    float g00x, float g00y, float g01x, float g01y,
    float g10x, float g10y, float g11x, float g11y)
{
    const int lowmask = bit - 1;
    const int i0 = ((tid & ~lowmask) << 1) | (tid & lowmask);
    const int i1 = i0 | bit;
    const float2 a = psi[i0], b = psi[i1];
    float2 n0, n1;
    n0.x = g00x*a.x - g00y*a.y + g01x*b.x - g01y*b.y;
    n0.y = g00x*a.y + g00y*a.x + g01x*b.y + g01y*b.x;
    n1.x = g10x*a.x - g10y*a.y + g11x*b.x - g11y*b.y;
    n1.y = g10x*a.y + g10y*a.x + g11x*b.y + g11y*b.x;
    psi[i0] = n0; psi[i1] = n1;
}

__global__ void qsa_circuit(const float* __restrict__ rx0,
                            const float* __restrict__ ry0,
                            const float* __restrict__ ry1)
{
    __shared__ float2 psi[DIM];
    const int tid = threadIdx.x;   // 512
    const int c = blockIdx.x;      // 0..63

    psi[tid]       = make_float2(0.f, 0.f);
    psi[tid + 512] = make_float2(0.f, 0.f);
    __syncthreads();
    if (tid == 0) psi[c] = make_float2(1.f, 0.f);
    __syncthreads();

    for (int j = 0; j < NW; j++) {
        const int bit = 1 << (NW - 1 - j);
        float s, cc;
        sincosf(0.5f * rx0[j], &s, &cc);
        gate1q(psi, tid, bit, cc, 0.f, 0.f, -s, 0.f, -s, cc, 0.f);
        __syncthreads();
        sincosf(0.5f * ry0[j], &s, &cc);
        gate1q(psi, tid, bit, cc, 0.f, -s, 0.f, s, 0.f, cc, 0.f);
        __syncthreads();
    }
    for (int j = 0; j < NW; j++) {
        const int cbit = 1 << (NW - 1 - j);
        const int tbit = 1 << (NW - 1 - ((j + 1) % NW));
        #pragma unroll
        for (int rep = 0; rep < 2; rep++) {
            const int i = tid + rep * 512;
            if ((i & cbit) && !(i & tbit)) {
                const float2 t = psi[i];
                psi[i] = psi[i | tbit];
                psi[i | tbit] = t;
            }
        }
        __syncthreads();
    }
    for (int j = 0; j < NW; j++) {
        const int bit = 1 << (NW - 1 - j);
        float s, cc;
        sincosf(0.5f * ry1[j], &s, &cc);
        gate1q(psi, tid, bit, cc, 0.f, -s, 0.f, s, 0.f, cc, 0.f);
        __syncthreads();
    }

    const int chunk = c >> 4;
    const int s  = (c >> 3) & 1;
    const int lq = (c & 7) >> 1;
    const int h  = c & 1;
    #pragma unroll
    for (int rep = 0; rep < 2; rep++) {
        const int i = tid + rep * 512;
        const float2 v = psi[i];
        #pragma unroll
        for (int p = 0; p < 2; p++) {
            const float val = p ? v.y : v.x;
            __nv_bfloat16 hi = __float2bfloat16(val);
            __nv_bfloat16 lo = __float2bfloat16(val - __bfloat162float(hi));
            const int n = 2 * i + p;
            const int tile = n >> 3;
            const int lane = (n & 7) * 4 + lq;
            const int idx = ((tile * 64 + (chunk >> 1) * 32 + lane) * 4
                             + (chunk & 1) * 2 + s) * 2 + h;
            WPH[idx] = __bfloat16_as_ushort(hi);
            WPL[idx] = __bfloat16_as_ushort(lo);
        }
    }
    // zero the padding tile so stray prefetches read defined memory
    if (c == 0 && tid < 256) {
        reinterpret_cast<uint4*>(WPH + 131072)[tid] = make_uint4(0,0,0,0);
        reinterpret_cast<uint4*>(WPL + 131072)[tid] = make_uint4(0,0,0,0);
    }
}

// ---------------------------------------------------------------------------
// HMMA helper
// ---------------------------------------------------------------------------
__device__ __forceinline__ void mma16816(float* c,
    const uint32_t* a, uint32_t b0, uint32_t b1)
{
    asm volatile(
        "mma.sync.aligned.m16n8k16.row.col.f32.bf16.bf16.f32 "
        "{%0,%1,%2,%3}, {%4,%5,%6,%7}, {%8,%9}, {%0,%1,%2,%3};"
        : "+f"(c[0]), "+f"(c[1]), "+f"(c[2]), "+f"(c[3])
        : "r"(a[0]), "r"(a[1]), "r"(a[2]), "r"(a[3]), "r"(b0), "r"(b1));
}

// ---------------------------------------------------------------------------
// Main kernel: 16 tokens/CTA, 8 warps; warp w handles tiles w + 8t (t=0..31).
// grid = 1024, 2 CTAs/SM.
// ---------------------------------------------------------------------------
__global__ void __launch_bounds__(256, 2) qsa_main(const float* __restrict__ x,
                                                   float* __restrict__ out)
{
    __shared__ float Y[16][64];
    __shared__ float Q[16][132];
    const int tid  = threadIdx.x;
    const int w    = tid >> 5;
    const int lane = tid & 31;
    const int m0   = blockIdx.x * 16;

    // --- load + L2-normalize 16 tokens ---
    {
        const int tk = tid >> 4;          // token 0..15
        const int pp = tid & 15;          // one float4 each
        const float4 f = reinterpret_cast<const float4*>(
            x + (size_t)(m0 + tk) * HID)[pp];
        float ssq = f.x*f.x + f.y*f.y + f.z*f.z + f.w*f.w;
        ssq += __shfl_xor_sync(0xffffffffu, ssq, 1);
        ssq += __shfl_xor_sync(0xffffffffu, ssq, 2);
        ssq += __shfl_xor_sync(0xffffffffu, ssq, 4);
        ssq += __shfl_xor_sync(0xffffffffu, ssq, 8);
        const float rn = rsqrtf(ssq);
        Y[tk][pp*4 + 0] = f.x * rn;
        Y[tk][pp*4 + 1] = f.y * rn;
        Y[tk][pp*4 + 2] = f.z * rn;
        Y[tk][pp*4 + 3] = f.w * rn;
    }
    __syncthreads();

    // --- A fragments: 4 k-chunks x 4 regs, hi/lo (16 tokens) ---
    uint32_t Ah[4][4], Al[4][4];
    {
        const int r0 = lane >> 2;
        const int q2 = (lane & 3) * 2;
        #pragma unroll
        for (int ch = 0; ch < 4; ch++)
            #pragma unroll
            for (int rg = 0; rg < 4; rg++) {
                const int row = r0 + 8*(rg & 1);
                const int k = ch*16 + q2 + 8*(rg >> 1);
                const float y0 = Y[row][k], y1 = Y[row][k+1];
                __nv_bfloat16 h0 = __float2bfloat16(y0);
                __nv_bfloat16 h1 = __float2bfloat16(y1);
                __nv_bfloat16 l0 = __float2bfloat16(y0 - __bfloat162float(h0));
                __nv_bfloat16 l1 = __float2bfloat16(y1 - __bfloat162float(h1));
                Ah[ch][rg] = ((uint32_t)__bfloat16_as_ushort(h1) << 16)
                           |  __bfloat16_as_ushort(h0);
                Al[ch][rg] = ((uint32_t)__bfloat16_as_ushort(l1) << 16)
                           |  __bfloat16_as_ushort(l0);
            }
    }

    // --- main loop: 32 tiles with register prefetch of next B tile ---
    float q[2][4];
    #pragma unroll
    for (int r = 0; r < 2; r++)
        #pragma unroll
        for (int s = 0; s < 4; s++) q[r][s] = 0.f;

    const uint4* pH = reinterpret_cast<const uint4*>(WPH) + w*64 + lane;
    const uint4* pL = reinterpret_cast<const uint4*>(WPL) + w*64 + lane;

    uint4 bh0 = pH[0], bh1 = pH[32];
    uint4 bl0 = pL[0], bl1 = pL[32];

    #pragma unroll 4
    for (int t = 0; t < 32; t++) {
        pH += 512; pL += 512;                       // tile += 8 (padded: safe at t=31)
        const uint4 nh0 = pH[0], nh1 = pH[32];
        const uint4 nl0 = pL[0], nl1 = pL[32];

        float hh[4] = {0.f,0.f,0.f,0.f};
        float lh[4] = {0.f,0.f,0.f,0.f};
        float hl[4] = {0.f,0.f,0.f,0.f};
        mma16816(hh, Ah[0], bh0.x, bh0.y);
        mma16816(lh, Al[0], bh0.x, bh0.y);
        mma16816(hl, Ah[0], bl0.x, bl0.y);
        mma16816(hh, Ah[1], bh0.z, bh0.w);
        mma16816(lh, Al[1], bh0.z, bh0.w);
        mma16816(hl, Ah[1], bl0.z, bl0.w);
        mma16816(hh, Ah[2], bh1.x, bh1.y);
        mma16816(lh, Al[2], bh1.x, bh1.y);
        mma16816(hl, Ah[2], bl1.x, bl1.y);
        mma16816(hh, Ah[3], bh1.z, bh1.w);
        mma16816(lh, Al[3], bh1.z, bh1.w);
        mma16816(hl, Ah[3], bl1.z, bl1.w);

        const int s = t & 3;
        const float c0 = hh[0] + lh[0] + hl[0];
        const float c1 = hh[1] + lh[1] + hl[1];
        const float c2 = hh[2] + lh[2] + hl[2];
        const float c3 = hh[3] + lh[3] + hl[3];
        q[0][s] = fmaf(c0, c0, fmaf(c1, c1, q[0][s]));
        q[1][s] = fmaf(c2, c2, fmaf(c3, c3, q[1][s]));

        bh0 = nh0; bh1 = nh1; bl0 = nl0; bl1 = nl1;
    }

    // --- scatter q into Q[token][j], j = 4w + 32s + (lane&3); disjoint per warp ---
    #pragma unroll
    for (int r = 0; r < 2; r++)
        #pragma unroll
        for (int s = 0; s < 4; s++) {
            const int tok = r*8 + (lane >> 2);
            const int j = 4*w + 32*s + (lane & 3);
            Q[tok][j] = q[r][s];
        }
    __syncthreads();

    // --- 128-pt WHT per token (warp w: tokens 2w, 2w+1), store out[k] = F[k+1] ---
    #pragma unroll
    for (int tt = 0; tt < 2; tt++) {
        const int tok = w*2 + tt;
        float f0 = Q[tok][lane];
        float f1 = Q[tok][lane + 32];
        float f2 = Q[tok][lane + 64];
        float f3 = Q[tok][lane + 96];
        float a0 = f0 + f1, a1 = f0 - f1, a2 = f2 + f3, a3 = f2 - f3;
        f0 = a0 + a2; f2 = a0 - a2; f1 = a1 + a3; f3 = a1 - a3;
        #pragma unroll
        for (int e = 1; e <= 16; e <<= 1) {
            float p;
            p = __shfl_xor_sync(0xffffffffu, f0, e); f0 = (lane & e) ? (p - f0) : (f0 + p);
            p = __shfl_xor_sync(0xffffffffu, f1, e); f1 = (lane & e) ? (p - f1) : (f1 + p);
            p = __shfl_xor_sync(0xffffffffu, f2, e); f2 = (lane & e) ? (p - f2) : (f2 + p);
        }
        float* orow = out + (size_t)(m0 + tok) * HID;
        if (lane >= 1) orow[lane - 1] = f0;     // F[1..31]  -> k 0..30
        orow[lane + 31] = f1;                   // F[32..63] -> k 31..62
        if (lane == 0) orow[63] = f2;           // F[64]     -> k 63
    }
}

extern "C" void kernel_launch(void* const* d_in, const int* in_sizes, int n_in,
                              void* d_out, int out_size)
{
    const float* x   = (const float*)d_in[0];
    const float* rx0 = (const float*)d_in[1];
    const float* ry0 = (const float*)d_in[2];
    const float* ry1 = (const float*)d_in[3];
    float* out = (float*)d_out;

    const int M = in_sizes[0] / HID;   // 16384 tokens

    qsa_circuit<<<HID, 512>>>(rx0, ry0, ry1);   // W -> packed HMMA B fragments
    qsa_main<<<M / 16, 256>>>(x, out);          // HMMA GEMM + fold + WHT epilogue
}